// round 9
// baseline (speedup 1.0000x reference)
#include <cuda_runtime.h>
#include <cuda_fp16.h>
#include <cstddef>

// Problem constants (match reference_code)
#define T_STEPS 600
#define N_REC   5000
#define N_IN    100
#define N_OUT   100
#define NR4     1250            // N_REC / 4 (float4 units)
#define KPAD    5056            // padded columns (= 32 * 158), zeros beyond 4999
#define NH2     2528            // half2 words per padded row (KPAD/2)
#define ROW_BYTES 10112         // NH2 * 4
#define NSLOTS  8               // TMA ring slots
#define P_PIN   6               // fp32 W rows pinned in SMEM per block (120 KB)
#define PTHREADS 768
#define BATCH   4               // stream rows per block-wide batch

// ---- dynamic smem layout ----
// rs    floats [0, 5056)               20224 B
// Wpin  floats [5056, 35056)          120000 B
// ring  bytes  [140224, 221120)        80896 B
// part  floats [55280, 55536)           1024 B
// mbar  bytes  [222144, 222208)           64 B
#define SM_TOTAL_BYTES 222208
#define RING_BYTE_OFF  140224
#define PART_FLT_OFF   55280
#define MBAR_BYTE_OFF  222144

// Scratch (allocation-free rule: __device__ globals)
__device__ float    g_x[N_REC];
__device__ float    g_drive[(size_t)T_STEPS * N_REC];
__device__ unsigned g_bar;
__device__ __align__(16) unsigned g_w16[(size_t)N_REC * NH2]; // interleaved fp16 rows

__device__ __forceinline__ unsigned ld_acq(const unsigned* p) {
    unsigned v;
    asm volatile("ld.global.acquire.gpu.u32 %0, [%1];" : "=r"(v) : "l"(p));
    return v;
}
__device__ __forceinline__ unsigned smem_u32(const void* p) {
    unsigned a;
    asm("{ .reg .u64 t; cvta.to.shared.u64 t, %1; cvt.u32.u64 %0, t; }" : "=r"(a) : "l"(p));
    return a;
}
__device__ __forceinline__ void mbar_init(unsigned mbar, unsigned cnt) {
    asm volatile("mbarrier.init.shared.b64 [%0], %1;" :: "r"(mbar), "r"(cnt) : "memory");
}
__device__ __forceinline__ void mbar_wait(unsigned mbar, unsigned parity) {
    asm volatile(
        "{\n\t.reg .pred P;\n"
        "W%=:\n\t"
        "mbarrier.try_wait.parity.shared.b64 P, [%0], %1, 0x989680;\n\t"
        "@P bra D%=;\n\t"
        "bra W%=;\n"
        "D%=:\n\t}"
        :: "r"(mbar), "r"(parity) : "memory");
}
__device__ __forceinline__ void issue_copy(unsigned ring_u32, unsigned mbar_base,
                                           const unsigned* src_row) {
    asm volatile("mbarrier.arrive.expect_tx.shared.b64 _, [%0], %1;"
                 :: "r"(mbar_base), "r"((unsigned)ROW_BYTES) : "memory");
    asm volatile("cp.async.bulk.shared::cta.global.mbarrier::complete_tx::bytes "
                 "[%0], [%1], %2, [%3];"
                 :: "r"(ring_u32), "l"(src_row), "r"((unsigned)ROW_BYTES),
                    "r"(mbar_base) : "memory");
}

// ---------------------------------------------------------------------------
// init: hidden[0] = r, x = arctanh(r), reset grid barrier
// ---------------------------------------------------------------------------
__global__ void init_kernel(const float* __restrict__ r, float* __restrict__ hidden) {
    int i = blockIdx.x * blockDim.x + threadIdx.x;
    if (i == 0) g_bar = 0u;
    if (i < N_REC) {
        float rv = r[i];
        hidden[i] = rv;
        g_x[i] = atanhf(rv);
    }
}

// ---------------------------------------------------------------------------
// convert streamed W rows to fp16, (column-pair, lane)-interleaved:
//   h2[sidx][jp*32 + l] = { w[64*jp + l], w[64*jp + 32 + l] }   (0 if k>=5000)
// ---------------------------------------------------------------------------
__global__ __launch_bounds__(256) void conv_kernel(
    const float* __restrict__ W, int pin_total, int n_stream)
{
    size_t e = (size_t)blockIdx.x * blockDim.x + threadIdx.x;
    size_t total = (size_t)n_stream * NH2;
    if (e >= total) return;
    int sidx = (int)(e / NH2);
    int i    = (int)(e % NH2);
    int jp = i >> 5, l = i & 31;
    int k1 = (jp << 6) + l;
    int k2 = k1 + 32;
    const float* src = W + (size_t)(pin_total + sidx) * N_REC;
    float a = (k1 < N_REC) ? src[k1] : 0.0f;
    float b = (k2 < N_REC) ? src[k2] : 0.0f;
    __half2 h = __floats2half2_rn(a, b);
    g_w16[(size_t)sidx * NH2 + i] = *(unsigned*)&h;
}

// ---------------------------------------------------------------------------
// drive[t][i] = sum_k u[t][k] * W_in[i][k] + eps[t][i]
// ---------------------------------------------------------------------------
#define DRIVE_TT 25
__global__ __launch_bounds__(128) void drive_kernel(
    const float* __restrict__ u, const float* __restrict__ W_in,
    const float* __restrict__ eps)
{
    __shared__ float us[DRIVE_TT][N_IN];
    int i  = blockIdx.x * 128 + threadIdx.x;
    int t0 = blockIdx.y * DRIVE_TT;

    for (int idx = threadIdx.x; idx < DRIVE_TT * N_IN; idx += 128) {
        int tl = idx / N_IN, k = idx % N_IN;
        us[tl][k] = u[(size_t)(t0 + tl) * N_IN + k];
    }
    __syncthreads();
    if (i >= N_REC) return;

    const float* __restrict__ Wr = W_in + (size_t)i * N_IN;
    for (int tl = 0; tl < DRIVE_TT; ++tl) {
        float acc = 0.0f;
        #pragma unroll 4
        for (int k = 0; k < N_IN; ++k)
            acc += __ldg(Wr + k) * us[tl][k];
        int t = t0 + tl;
        g_drive[(size_t)t * N_REC + i] = acc + eps[(size_t)t * N_REC + i];
    }
}

__device__ __forceinline__ float warp_reduce(float s) {
    #pragma unroll
    for (int o = 16; o; o >>= 1) s += __shfl_xor_sync(0xffffffffu, s, o);
    return s;
}

// ---------------------------------------------------------------------------
// Persistent RNN rollout.
//   - 6 fp32 rows pinned in SMEM; ~28 fp16 rows/block streamed via
//     cp.async.bulk (UBLKCP) into an 8-slot mbarrier ring; prefetch runs
//     across step boundaries (W is step-invariant).
//   - block-wide dots (768 threads), conflict-free smem layout, 4-row
//     batches sharing r loads, double-buffered partial reduction.
//   - 222 KB smem -> occupancy 1; grid == #SMs -> single wave; atomic
//     grid barrier cannot deadlock.
// ---------------------------------------------------------------------------
__global__ __launch_bounds__(PTHREADS, 1) void rnn_persistent(
    float* __restrict__ hidden, const float* __restrict__ W,
    int G, int pin_total, int n_stream)
{
    extern __shared__ float sm[];
    float*    rs      = sm;                         // [KPAD]
    float*    Wpin    = sm + KPAD;                  // [P_PIN * N_REC]
    unsigned* ring    = (unsigned*)((char*)sm + RING_BYTE_OFF);
    float*    part    = sm + PART_FLT_OFF;          // [2][4][32]
    unsigned  mbar0   = smem_u32((char*)sm + MBAR_BYTE_OFF);
    unsigned  ring0   = smem_u32(ring);

    const int b    = blockIdx.x;
    const int tid  = threadIdx.x;
    const int warp = tid >> 5;
    const int lane = tid & 31;

    // this block's stream range
    const int base = n_stream / G, rem = n_stream % G;
    const int ns    = base + (b < rem ? 1 : 0);
    const int start = b * base + (b < rem ? b : rem);
    const size_t total_copies = (size_t)T_STEPS * ns;

    // zero r padding (floats 5000..5055); stage loop never writes there
    if (tid < KPAD - N_REC) rs[N_REC + tid] = 0.0f;

    // pin fp32 rows
    {
        const float4* src = (const float4*)(W + (size_t)b * P_PIN * N_REC);
        float4* dst = (float4*)Wpin;
        for (int i = tid; i < P_PIN * NR4; i += PTHREADS) dst[i] = src[i];
    }

    // mbarriers, fence, then prologue copies
    if (tid == 0) {
        for (int s = 0; s < NSLOTS; ++s) mbar_init(mbar0 + s * 8, 1);
        asm volatile("fence.proxy.async.shared::cta;" ::: "memory");
    }
    __syncthreads();
    if (tid == 0) {
        for (size_t c = 0; c < NSLOTS && c < total_copies; ++c) {
            int slot = (int)(c % NSLOTS);
            int q    = (int)(c % ns);
            issue_copy(ring0 + slot * ROW_BYTES, mbar0 + slot * 8,
                       g_w16 + (size_t)(start + q) * NH2);
        }
    }

    int beta = 0;

    for (int t = 0; t < T_STEPS; ++t) {
        // stage r_prev = hidden[t]
        {
            const float4* rg = (const float4*)(hidden + (size_t)t * N_REC);
            float4* rd = (float4*)rs;
            for (int i = tid; i < NR4; i += PTHREADS) rd[i] = rg[i];
        }
        __syncthreads();

        // ---- pinned rows, batches of 4 (6 rows: 4 + 2) ----
        for (int r0 = 0; r0 < P_PIN; r0 += BATCH) {
            const int nr = (P_PIN - r0 < BATCH) ? (P_PIN - r0) : BATCH;
            float acc[BATCH] = {0.f, 0.f, 0.f, 0.f};
            const float4* rs4 = (const float4*)rs;
            #pragma unroll
            for (int z = 0; z < 2; ++z) {
                int idx = tid + z * PTHREADS;
                if (idx < NR4) {
                    float4 rv = rs4[idx];
                    #pragma unroll
                    for (int rr = 0; rr < BATCH; ++rr) {
                        if (rr < nr) {
                            float4 w = ((const float4*)Wpin)[(r0 + rr) * NR4 + idx];
                            acc[rr] += w.x*rv.x + w.y*rv.y + w.z*rv.z + w.w*rv.w;
                        }
                    }
                }
            }
            #pragma unroll
            for (int rr = 0; rr < BATCH; ++rr) {
                float v = warp_reduce(acc[rr]);
                if (lane == 0) part[beta * 128 + rr * 32 + warp] = v;
            }
            __syncthreads();
            if (warp < nr) {
                float v = (lane < PTHREADS / 32) ? part[beta * 128 + warp * 32 + lane] : 0.f;
                v = warp_reduce(v);
                if (lane == 0) {
                    int row = b * P_PIN + r0 + warp;
                    float x = g_x[row];
                    x = 0.9f * x + 0.1f * (v + g_drive[(size_t)t * N_REC + row]);
                    g_x[row] = x;
                    hidden[(size_t)(t + 1) * N_REC + row] = tanhf(x);
                }
            }
            beta ^= 1;
        }

        // ---- streamed rows, batches of 4 from the TMA ring ----
        const size_t c0 = (size_t)t * ns;
        for (int q0 = 0; q0 < ns; q0 += BATCH) {
            const int nr = (ns - q0 < BATCH) ? (ns - q0) : BATCH;
            #pragma unroll
            for (int j = 0; j < BATCH; ++j) {
                if (j < nr) {
                    size_t c = c0 + q0 + j;
                    mbar_wait(mbar0 + (unsigned)(c % NSLOTS) * 8,
                              (unsigned)((c / NSLOTS) & 1));
                }
            }
            const unsigned* slotp[BATCH];
            #pragma unroll
            for (int j = 0; j < BATCH; ++j)
                slotp[j] = ring + ((c0 + q0 + j) % NSLOTS) * NH2;

            float acc[BATCH] = {0.f, 0.f, 0.f, 0.f};
            #pragma unroll
            for (int z = 0; z < 4; ++z) {
                int i = tid + z * PTHREADS;
                if (i < NH2) {
                    int jp = i >> 5, l = i & 31;
                    int k  = (jp << 6) + l;
                    float rv1 = rs[k];
                    float rv2 = rs[k + 32];
                    #pragma unroll
                    for (int rr = 0; rr < BATCH; ++rr) {
                        if (rr < nr) {
                            unsigned h = slotp[rr][i];
                            float2 wf = __half22float2(*(const __half2*)&h);
                            acc[rr] += wf.x * rv1 + wf.y * rv2;
                        }
                    }
                }
            }
            #pragma unroll
            for (int rr = 0; rr < BATCH; ++rr) {
                float v = warp_reduce(acc[rr]);
                if (lane == 0) part[beta * 128 + rr * 32 + warp] = v;
            }
            __syncthreads();   // batch consumed: slots c0+q0..+nr-1 now free
            if (tid == 0) {    // refill freed slots (prefetch into next step ok)
                #pragma unroll
                for (int j = 0; j < BATCH; ++j) {
                    size_t c = c0 + q0 + j + NSLOTS;
                    if (j < nr && c < total_copies) {
                        int slot = (int)(c % NSLOTS);
                        int q    = (int)(c % ns);
                        issue_copy(ring0 + slot * ROW_BYTES, mbar0 + slot * 8,
                                   g_w16 + (size_t)(start + q) * NH2);
                    }
                }
            }
            if (warp < nr) {
                float v = (lane < PTHREADS / 32) ? part[beta * 128 + warp * 32 + lane] : 0.f;
                v = warp_reduce(v);
                if (lane == 0) {
                    int row = pin_total + start + q0 + warp;
                    float x = g_x[row];
                    x = 0.9f * x + 0.1f * (v + g_drive[(size_t)t * N_REC + row]);
                    g_x[row] = x;
                    hidden[(size_t)(t + 1) * N_REC + row] = tanhf(x);
                }
            }
            beta ^= 1;
        }

        __syncthreads();   // all x-updates done before arriving

        // grid barrier
        if (tid == 0) {
            __threadfence();
            atomicAdd(&g_bar, 1u);
            unsigned tgt = (unsigned)G * (unsigned)(t + 1);
            while (ld_acq(&g_bar) < tgt) __nanosleep(64);
        }
        __syncthreads();
    }
}

// ---------------------------------------------------------------------------
// out: o[t][j] = sum_i hidden[t+1][i] * W_out[j][i]
// ---------------------------------------------------------------------------
#define OUT_OT 2
__global__ __launch_bounds__(512) void out_kernel(
    const float* __restrict__ hidden, const float* __restrict__ W_out,
    float* __restrict__ o)
{
    __shared__ float4 rsh[OUT_OT][NR4];
    int tid = threadIdx.x;
    int t0  = blockIdx.x * OUT_OT;

    for (int i = tid; i < OUT_OT * NR4; i += 512) {
        int tl = i / NR4, v = i % NR4;
        rsh[tl][v] = ((const float4*)(hidden + (size_t)(t0 + tl + 1) * N_REC))[v];
    }
    __syncthreads();

    int w    = tid >> 5;
    int lane = tid & 31;

    for (int task = w; task < N_OUT * OUT_OT; task += 16) {
        int j  = task >> 1;
        int tl = task & 1;
        const float4* __restrict__ Wr = (const float4*)(W_out + (size_t)j * N_REC);
        const float4* __restrict__ rr = rsh[tl];

        float4 a = make_float4(0.f, 0.f, 0.f, 0.f);
        #pragma unroll 8
        for (int v = lane; v < NR4; v += 32) {
            float4 wv = __ldg(Wr + v);
            float4 rv = rr[v];
            a.x += wv.x * rv.x;
            a.y += wv.y * rv.y;
            a.z += wv.z * rv.z;
            a.w += wv.w * rv.w;
        }
        float s = warp_reduce((a.x + a.y) + (a.z + a.w));
        if (lane == 0) o[(size_t)(t0 + tl) * N_OUT + j] = s;
    }
}

// ---------------------------------------------------------------------------
// kernel_launch (graph-capturable, allocation-free)
// Inputs: 0:u [600,100] 1:r [5000] 2:W_in [5000,100] 3:W_rec [5000,5000]
//         4:W_out [100,5000] 5:eps [600,5000]
// Output: hidden_states [601,5000] then o [600,100]
// ---------------------------------------------------------------------------
extern "C" void kernel_launch(void* const* d_in, const int* in_sizes, int n_in,
                              void* d_out, int out_size)
{
    const float* u     = (const float*)d_in[0];
    const float* r     = (const float*)d_in[1];
    const float* W_in  = (const float*)d_in[2];
    const float* W_rec = (const float*)d_in[3];
    const float* W_out = (const float*)d_in[4];
    const float* eps   = (const float*)d_in[5];

    float* hidden = (float*)d_out;                          // [601, 5000]
    float* o      = hidden + (size_t)(T_STEPS + 1) * N_REC; // [600, 100]

    int dev = 0, sms = 148;
    cudaGetDevice(&dev);
    cudaDeviceGetAttribute(&sms, cudaDevAttrMultiProcessorCount, dev);
    int G = sms;
    if (G < 1) G = 1;
    const int pin_total = G * P_PIN;     // 888 @148 SMs
    const int n_stream  = N_REC - pin_total;

    cudaFuncSetAttribute(rnn_persistent,
                         cudaFuncAttributeMaxDynamicSharedMemorySize, SM_TOTAL_BYTES);

    init_kernel<<<(N_REC + 255) / 256, 256>>>(r, hidden);

    const size_t conv_total = (size_t)n_stream * NH2;
    conv_kernel<<<(unsigned)((conv_total + 255) / 256), 256>>>(W_rec, pin_total, n_stream);

    dim3 dgrid((N_REC + 127) / 128, T_STEPS / DRIVE_TT);
    drive_kernel<<<dgrid, 128>>>(u, W_in, eps);

    rnn_persistent<<<G, PTHREADS, SM_TOTAL_BYTES>>>(hidden, W_rec, G, pin_total, n_stream);

    out_kernel<<<T_STEPS / OUT_OT, 512>>>(hidden, W_out, o);
}

// round 10
// speedup vs baseline: 2.0314x; 2.0314x over previous
#include <cuda_runtime.h>
#include <cuda_fp16.h>
#include <cstddef>

// Problem constants (match reference_code)
#define T_STEPS 600
#define N_REC   5000
#define N_IN    100
#define N_OUT   100
#define NR4     1250            // N_REC / 4
#define KPAD    5120            // padded columns (20 groups of 256)
#define NWU4    640             // uint4 words per fp16 row (KPAD/8)
#define NH2W    2560            // half2 words per fp16 row
#define P_PIN   18              // fp16 rows pinned in SMEM per block
#define PTHREADS 768
#define NWARPS  24

// smem: rs [0,20480) | Wpin [20480,204800) | part [204800,205072)
#define SM_TOTAL_BYTES 205072

// Scratch (allocation-free rule: __device__ globals)
__device__ float    g_x[N_REC];
__device__ float    g_drive[(size_t)T_STEPS * N_REC];
__device__ unsigned g_bar;
__device__ __align__(16) unsigned g_w16[(size_t)N_REC * NH2W]; // 51.2 MB fp16 W

__device__ __forceinline__ unsigned ld_acq(const unsigned* p) {
    unsigned v;
    asm volatile("ld.global.acquire.gpu.u32 %0, [%1];" : "=r"(v) : "l"(p));
    return v;
}
__device__ __forceinline__ float warp_reduce(float s) {
    #pragma unroll
    for (int o = 16; o; o >>= 1) s += __shfl_xor_sync(0xffffffffu, s, o);
    return s;
}

// ---------------------------------------------------------------------------
// init: hidden[0] = r, x = arctanh(r), reset grid barrier
// ---------------------------------------------------------------------------
__global__ void init_kernel(const float* __restrict__ r, float* __restrict__ hidden) {
    int i = blockIdx.x * blockDim.x + threadIdx.x;
    if (i == 0) g_bar = 0u;
    if (i < N_REC) {
        float rv = r[i];
        hidden[i] = rv;
        g_x[i] = atanhf(rv);
    }
}

// ---------------------------------------------------------------------------
// convert ALL W rows to fp16, (c, c+32)-pair interleaved uint4 layout:
//   half2 word w of a row: i=w>>2 (uint4 idx), k=w&3, jp=i>>5, l=i&31
//   -> cols c1 = 256*jp + 64*k + l, c2 = c1 + 32   (0 if col >= 5000)
// ---------------------------------------------------------------------------
__global__ __launch_bounds__(256) void conv_kernel(const float* __restrict__ W) {
    size_t e = (size_t)blockIdx.x * blockDim.x + threadIdx.x;
    if (e >= (size_t)N_REC * NH2W) return;
    int row = (int)(e / NH2W);
    int w   = (int)(e % NH2W);
    int i = w >> 2, k = w & 3;
    int jp = i >> 5, l = i & 31;
    int c1 = (jp << 8) + (k << 6) + l;
    int c2 = c1 + 32;
    const float* src = W + (size_t)row * N_REC;
    float a = (c1 < N_REC) ? src[c1] : 0.0f;
    float b = (c2 < N_REC) ? src[c2] : 0.0f;
    __half2 h = __floats2half2_rn(a, b);
    g_w16[e] = *(unsigned*)&h;
}

// ---------------------------------------------------------------------------
// drive[t][i] = sum_k u[t][k] * W_in[i][k] + eps[t][i]
// ---------------------------------------------------------------------------
#define DRIVE_TT 25
__global__ __launch_bounds__(128) void drive_kernel(
    const float* __restrict__ u, const float* __restrict__ W_in,
    const float* __restrict__ eps)
{
    __shared__ float us[DRIVE_TT][N_IN];
    int i  = blockIdx.x * 128 + threadIdx.x;
    int t0 = blockIdx.y * DRIVE_TT;

    for (int idx = threadIdx.x; idx < DRIVE_TT * N_IN; idx += 128) {
        int tl = idx / N_IN, k = idx % N_IN;
        us[tl][k] = u[(size_t)(t0 + tl) * N_IN + k];
    }
    __syncthreads();
    if (i >= N_REC) return;

    const float* __restrict__ Wr = W_in + (size_t)i * N_IN;
    for (int tl = 0; tl < DRIVE_TT; ++tl) {
        float acc = 0.0f;
        #pragma unroll 4
        for (int k = 0; k < N_IN; ++k)
            acc += __ldg(Wr + k) * us[tl][k];
        int t = t0 + tl;
        g_drive[(size_t)t * N_REC + i] = acc + eps[(size_t)t * N_REC + i];
    }
}

// half-row dot: columns [h*2560, h*2560+2560) of one fp16 row.
// GLB=true -> W from global (L2-resident), else from SMEM (conflict-free).
template <bool GLB>
__device__ __forceinline__ float half_dot(const uint4* __restrict__ Wr,
                                          const float* __restrict__ rs,
                                          int h, int lane)
{
    float a0 = 0.f, a1 = 0.f;
    #pragma unroll
    for (int jj = 0; jj < 10; ++jj) {
        int jp = h * 10 + jj;
        uint4 q = GLB ? __ldg(Wr + (jp << 5) + lane) : Wr[(jp << 5) + lane];
        int cb = (jp << 8) + lane;
        float2 f0 = __half22float2(*reinterpret_cast<const __half2*>(&q.x));
        float2 f1 = __half22float2(*reinterpret_cast<const __half2*>(&q.y));
        float2 f2 = __half22float2(*reinterpret_cast<const __half2*>(&q.z));
        float2 f3 = __half22float2(*reinterpret_cast<const __half2*>(&q.w));
        a0 += f0.x * rs[cb]       + f0.y * rs[cb + 32];
        a1 += f1.x * rs[cb + 64]  + f1.y * rs[cb + 96];
        a0 += f2.x * rs[cb + 128] + f2.y * rs[cb + 160];
        a1 += f3.x * rs[cb + 192] + f3.y * rs[cb + 224];
    }
    return a0 + a1;
}

// ---------------------------------------------------------------------------
// Persistent RNN rollout, warp-per-half-row.
//   - block owns ~34 contiguous rows; first 18 pinned in SMEM (fp16),
//     rest streamed by __ldg from L2 (23.9 MB/step chip-wide, resident).
//   - 68 half-row tasks over 24 warps; only warp_reduce + 4 syncs/step.
//   - 205 KB smem -> occupancy 1; grid == #SMs -> barrier is safe.
// ---------------------------------------------------------------------------
__global__ __launch_bounds__(PTHREADS, 1) void rnn_persistent(
    float* __restrict__ hidden, int G)
{
    extern __shared__ float sm[];
    float* rs   = sm;                                  // [KPAD]
    uint4* Wpin = (uint4*)(sm + KPAD);                 // [P_PIN * NWU4]
    float* part = sm + KPAD + P_PIN * NWU4 * 4;        // [2 * nrows]

    const int b    = blockIdx.x;
    const int tid  = threadIdx.x;
    const int warp = tid >> 5;
    const int lane = tid & 31;

    // contiguous row range for this block
    const int base = N_REC / G, rem = N_REC % G;
    const int nrows  = base + (b < rem ? 1 : 0);
    const int rstart = b * base + (b < rem ? b : rem);
    const int ntasks = 2 * nrows;

    // zero rs padding (cols 5000..5119); stage loop never writes there
    if (tid < KPAD - N_REC) rs[N_REC + tid] = 0.0f;

    // pin first P_PIN rows (contiguous in g_w16)
    {
        const uint4* src = (const uint4*)g_w16 + (size_t)rstart * NWU4;
        for (int i = tid; i < P_PIN * NWU4; i += PTHREADS) Wpin[i] = src[i];
    }

    const uint4* gW = (const uint4*)g_w16;

    for (int t = 0; t < T_STEPS; ++t) {
        // stage r_prev = hidden[t] (exactly 5000 floats = 1250 float4)
        {
            const float4* rg = (const float4*)(hidden + (size_t)t * N_REC);
            float4* rd = (float4*)rs;
            for (int i = tid; i < NR4; i += PTHREADS) rd[i] = rg[i];
        }
        __syncthreads();

        // half-row tasks
        for (int tau = warp; tau < ntasks; tau += NWARPS) {
            int local = tau >> 1;
            int h     = tau & 1;
            float acc;
            if (local < P_PIN)
                acc = half_dot<false>(Wpin + local * NWU4, rs, h, lane);
            else
                acc = half_dot<true>(gW + (size_t)(rstart + local) * NWU4, rs, h, lane);
            acc = warp_reduce(acc);
            if (lane == 0) part[tau] = acc;
        }
        __syncthreads();

        // combine halves + state update (one thread per row)
        if (tid < nrows) {
            int row = rstart + tid;
            float y = part[2 * tid] + part[2 * tid + 1];
            float x = g_x[row];
            x = 0.9f * x + 0.1f * (y + g_drive[(size_t)t * N_REC + row]);
            g_x[row] = x;
            hidden[(size_t)(t + 1) * N_REC + row] = tanhf(x);
        }
        __syncthreads();

        // grid barrier
        if (tid == 0) {
            __threadfence();
            atomicAdd(&g_bar, 1u);
            unsigned tgt = (unsigned)G * (unsigned)(t + 1);
            while (ld_acq(&g_bar) < tgt) __nanosleep(64);
        }
        __syncthreads();
    }
}

// ---------------------------------------------------------------------------
// out: o[t][j] = sum_i hidden[t+1][i] * W_out[j][i]
// ---------------------------------------------------------------------------
#define OUT_OT 2
__global__ __launch_bounds__(512) void out_kernel(
    const float* __restrict__ hidden, const float* __restrict__ W_out,
    float* __restrict__ o)
{
    __shared__ float4 rsh[OUT_OT][NR4];
    int tid = threadIdx.x;
    int t0  = blockIdx.x * OUT_OT;

    for (int i = tid; i < OUT_OT * NR4; i += 512) {
        int tl = i / NR4, v = i % NR4;
        rsh[tl][v] = ((const float4*)(hidden + (size_t)(t0 + tl + 1) * N_REC))[v];
    }
    __syncthreads();

    int w    = tid >> 5;
    int lane = tid & 31;

    for (int task = w; task < N_OUT * OUT_OT; task += 16) {
        int j  = task >> 1;
        int tl = task & 1;
        const float4* __restrict__ Wr = (const float4*)(W_out + (size_t)j * N_REC);
        const float4* __restrict__ rr = rsh[tl];

        float4 a = make_float4(0.f, 0.f, 0.f, 0.f);
        #pragma unroll 8
        for (int v = lane; v < NR4; v += 32) {
            float4 wv = __ldg(Wr + v);
            float4 rv = rr[v];
            a.x += wv.x * rv.x;
            a.y += wv.y * rv.y;
            a.z += wv.z * rv.z;
            a.w += wv.w * rv.w;
        }
        float s = warp_reduce((a.x + a.y) + (a.z + a.w));
        if (lane == 0) o[(size_t)(t0 + tl) * N_OUT + j] = s;
    }
}

// ---------------------------------------------------------------------------
// kernel_launch (graph-capturable, allocation-free)
// Inputs: 0:u [600,100] 1:r [5000] 2:W_in [5000,100] 3:W_rec [5000,5000]
//         4:W_out [100,5000] 5:eps [600,5000]
// Output: hidden_states [601,5000] then o [600,100]
// ---------------------------------------------------------------------------
extern "C" void kernel_launch(void* const* d_in, const int* in_sizes, int n_in,
                              void* d_out, int out_size)
{
    const float* u     = (const float*)d_in[0];
    const float* r     = (const float*)d_in[1];
    const float* W_in  = (const float*)d_in[2];
    const float* W_rec = (const float*)d_in[3];
    const float* W_out = (const float*)d_in[4];
    const float* eps   = (const float*)d_in[5];

    float* hidden = (float*)d_out;                          // [601, 5000]
    float* o      = hidden + (size_t)(T_STEPS + 1) * N_REC; // [600, 100]

    int dev = 0, sms = 148;
    cudaGetDevice(&dev);
    cudaDeviceGetAttribute(&sms, cudaDevAttrMultiProcessorCount, dev);
    int G = sms;
    if (G < 1) G = 1;

    cudaFuncSetAttribute(rnn_persistent,
                         cudaFuncAttributeMaxDynamicSharedMemorySize, SM_TOTAL_BYTES);

    init_kernel<<<(N_REC + 255) / 256, 256>>>(r, hidden);

    const size_t conv_total = (size_t)N_REC * NH2W;         // 12.8M words
    conv_kernel<<<(unsigned)((conv_total + 255) / 256), 256>>>(W_rec);

    dim3 dgrid((N_REC + 127) / 128, T_STEPS / DRIVE_TT);
    drive_kernel<<<dgrid, 128>>>(u, W_in, eps);

    rnn_persistent<<<G, PTHREADS, SM_TOTAL_BYTES>>>(hidden, G);

    out_kernel<<<T_STEPS / OUT_OT, 512>>>(hidden, W_out, o);
}